// round 3
// baseline (speedup 1.0000x reference)
#include <cuda_runtime.h>
#include <math.h>

// Problem constants
#define BATCH 4096
#define DIN   1024
#define DOUT  1024
#define D2    2048   // 2*OUT
#define D3    3072   // 3*OUT

// GEMM tiling
#define BM 128
#define BN 128
#define BK 16
#define TM 8
#define TN 8
#define NTHREADS 256

// Scratch (allocation-free requirement -> __device__ globals)
__device__ float g_act[(size_t)BATCH * D2];   // activated [B, 2*OUT]
__device__ float g_z[(size_t)BATCH * DOUT];   // z gate    [B, OUT]
__device__ float g_rh[(size_t)BATCH * DOUT];  // r*h_prev  [B, OUT]

struct SmemT {
    float As[BK][BM];
    float Bs[BK][BN];
};

// Segmented-K GEMM core: A is logically [M, Ktot] = [A0 (cols 0..K0) | A1 (cols K0..Ktot)],
// both row-major with their own leading dims. B is row-major [Ktot, ldb], starting col n0.
// Computes acc += A[m0:m0+128, :] @ B[:, n0:n0+128] for this block's 128x128 tile.
__device__ __forceinline__ void gemm_core(
    const float* __restrict__ A0, int lda0,
    const float* __restrict__ A1, int lda1, int K0,
    const float* __restrict__ B, int ldb, int Ktot,
    int m0, int n0, float acc[TM][TN], SmemT& s)
{
    const int tid = threadIdx.x;
    const int tx = tid & 15;        // 0..15 (n direction)
    const int ty = tid >> 4;        // 0..15 (m direction)

    for (int kt = 0; kt < Ktot; kt += BK) {
        const float* Aseg;
        int lda;
        if (kt < K0) { Aseg = A0 + kt;        lda = lda0; }
        else         { Aseg = A1 + (kt - K0); lda = lda1; }

        // Load A tile (BM x BK), store transposed As[k][m]
        #pragma unroll
        for (int i = 0; i < 2; i++) {
            int idx = tid + i * NTHREADS;          // 0..511
            int row = idx >> 2;                    // 0..127
            int kc  = (idx & 3) * 4;               // 0,4,8,12
            float4 v = *(const float4*)(Aseg + (size_t)(m0 + row) * lda + kc);
            s.As[kc + 0][row] = v.x;
            s.As[kc + 1][row] = v.y;
            s.As[kc + 2][row] = v.z;
            s.As[kc + 3][row] = v.w;
        }
        // Load B tile (BK x BN)
        #pragma unroll
        for (int i = 0; i < 2; i++) {
            int idx = tid + i * NTHREADS;          // 0..511
            int row = idx >> 5;                    // 0..15
            int c   = (idx & 31) * 4;              // 0..124
            *(float4*)&s.Bs[row][c] =
                *(const float4*)(B + (size_t)(kt + row) * ldb + n0 + c);
        }
        __syncthreads();

        #pragma unroll
        for (int k = 0; k < BK; k++) {
            float a[TM], b[TN];
            *(float4*)&a[0] = *(const float4*)&s.As[k][ty * TM];
            *(float4*)&a[4] = *(const float4*)&s.As[k][ty * TM + 4];
            *(float4*)&b[0] = *(const float4*)&s.Bs[k][tx * TN];
            *(float4*)&b[4] = *(const float4*)&s.Bs[k][tx * TN + 4];
            #pragma unroll
            for (int i = 0; i < TM; i++)
                #pragma unroll
                for (int j = 0; j < TN; j++)
                    acc[i][j] = fmaf(a[i], b[j], acc[i][j]);
        }
        __syncthreads();
    }
}

// ---------------------------------------------------------------------------
// Kernel 1: new_x = [x, h_prev] @ W_in + b_in; spike logic; writes g_act and
// pot_next (into d_out's pot section).
// ---------------------------------------------------------------------------
__global__ __launch_bounds__(NTHREADS)
void k1_input_gemm(const float* __restrict__ x,
                   const float* __restrict__ h_prev,
                   const float* __restrict__ pot_prev,
                   const float* __restrict__ W_in,
                   const float* __restrict__ b_in,
                   const float* __restrict__ tresh,
                   const float* __restrict__ decay,
                   float* __restrict__ pot_out)
{
    __shared__ SmemT s;
    float acc[TM][TN];
    #pragma unroll
    for (int i = 0; i < TM; i++)
        #pragma unroll
        for (int j = 0; j < TN; j++) acc[i][j] = 0.f;

    const int m0 = blockIdx.y * BM;
    const int n0 = blockIdx.x * BN;

    gemm_core(x, DIN, h_prev, DOUT, DIN, W_in, D2, DIN + DOUT, m0, n0, acc, s);

    const int tx = threadIdx.x & 15;
    const int ty = threadIdx.x >> 4;

    float bin[TN], th[TN], dc[TN];
    #pragma unroll
    for (int j = 0; j < TN; j++) {
        int n = n0 + tx * TN + j;
        bin[j] = b_in[n];
        th[j]  = tresh[n];
        dc[j]  = decay[n];
    }

    #pragma unroll
    for (int i = 0; i < TM; i++) {
        int m = m0 + ty * TM + i;
        size_t base = (size_t)m * D2 + n0 + tx * TN;
        float av[TN], pv[TN];
        #pragma unroll
        for (int j = 0; j < TN; j++) {
            float pt = pot_prev[base + j] + acc[i][j] + bin[j];
            bool spiked = pt > th[j];
            av[j] = spiked ? pt : 0.f;
            pv[j] = spiked ? 0.f : pt * dc[j];
        }
        #pragma unroll
        for (int j = 0; j < TN; j += 4) {
            *(float4*)&g_act[base + j]  = *(float4*)&av[j];
            *(float4*)&pot_out[base + j] = *(float4*)&pv[j];
        }
    }
}

// ---------------------------------------------------------------------------
// Kernel 2: z and r gates. Logical N = 2048 (first 1024 -> z, second -> r).
// A = [g_act, h_prev] (K = 3072). z stored to g_z; r combined as g_rh = h*r.
// ---------------------------------------------------------------------------
__global__ __launch_bounds__(NTHREADS)
void k2_zr_gemm(const float* __restrict__ h_prev,
                const float* __restrict__ W_z,
                const float* __restrict__ b_z,
                const float* __restrict__ W_r,
                const float* __restrict__ b_r)
{
    __shared__ SmemT s;
    float acc[TM][TN];
    #pragma unroll
    for (int i = 0; i < TM; i++)
        #pragma unroll
        for (int j = 0; j < TN; j++) acc[i][j] = 0.f;

    const int m0 = blockIdx.y * BM;
    const int n0g = blockIdx.x * BN;      // global 0..2047
    const bool isZ = (n0g < DOUT);
    const int n0 = isZ ? n0g : (n0g - DOUT);
    const float* W  = isZ ? W_z : W_r;
    const float* bs = isZ ? b_z : b_r;

    gemm_core(g_act, D2, h_prev, DOUT, D2, W, DOUT, D3, m0, n0, acc, s);

    const int tx = threadIdx.x & 15;
    const int ty = threadIdx.x >> 4;

    float bb[TN];
    #pragma unroll
    for (int j = 0; j < TN; j++) bb[j] = bs[n0 + tx * TN + j];

    #pragma unroll
    for (int i = 0; i < TM; i++) {
        int m = m0 + ty * TM + i;
        size_t base = (size_t)m * DOUT + n0 + tx * TN;
        float out[TN];
        #pragma unroll
        for (int j = 0; j < TN; j++) {
            float sg = 1.f / (1.f + expf(-(acc[i][j] + bb[j])));
            out[j] = isZ ? sg : sg * h_prev[base + j];
        }
        float* dst = isZ ? g_z : g_rh;
        #pragma unroll
        for (int j = 0; j < TN; j += 4)
            *(float4*)&dst[base + j] = *(float4*)&out[j];
    }
}

// ---------------------------------------------------------------------------
// Kernel 3: n = tanh([g_act, g_rh] @ W_n + b_n); h_next = (1-z)*h + z*n.
// ---------------------------------------------------------------------------
__global__ __launch_bounds__(NTHREADS)
void k3_cand_gemm(const float* __restrict__ h_prev,
                  const float* __restrict__ W_n,
                  const float* __restrict__ b_n,
                  float* __restrict__ h_out)
{
    __shared__ SmemT s;
    float acc[TM][TN];
    #pragma unroll
    for (int i = 0; i < TM; i++)
        #pragma unroll
        for (int j = 0; j < TN; j++) acc[i][j] = 0.f;

    const int m0 = blockIdx.y * BM;
    const int n0 = blockIdx.x * BN;

    gemm_core(g_act, D2, g_rh, DOUT, D2, W_n, DOUT, D3, m0, n0, acc, s);

    const int tx = threadIdx.x & 15;
    const int ty = threadIdx.x >> 4;

    float bb[TN];
    #pragma unroll
    for (int j = 0; j < TN; j++) bb[j] = b_n[n0 + tx * TN + j];

    #pragma unroll
    for (int i = 0; i < TM; i++) {
        int m = m0 + ty * TM + i;
        size_t base = (size_t)m * DOUT + n0 + tx * TN;
        float out[TN];
        #pragma unroll
        for (int j = 0; j < TN; j++) {
            float nv = tanhf(acc[i][j] + bb[j]);
            float z  = g_z[base + j];
            out[j] = (1.f - z) * h_prev[base + j] + z * nv;
        }
        #pragma unroll
        for (int j = 0; j < TN; j += 4)
            *(float4*)&h_out[base + j] = *(float4*)&out[j];
    }
}

// ---------------------------------------------------------------------------
// Launch
// ---------------------------------------------------------------------------
extern "C" void kernel_launch(void* const* d_in, const int* in_sizes, int n_in,
                              void* d_out, int out_size)
{
    const float* x        = (const float*)d_in[0];
    const float* h_prev   = (const float*)d_in[1];
    const float* pot_prev = (const float*)d_in[2];
    const float* W_in     = (const float*)d_in[3];
    const float* b_in     = (const float*)d_in[4];
    const float* tresh    = (const float*)d_in[5];
    const float* decay    = (const float*)d_in[6];
    const float* W_z      = (const float*)d_in[7];
    const float* b_z      = (const float*)d_in[8];
    const float* W_r      = (const float*)d_in[9];
    const float* b_r      = (const float*)d_in[10];
    const float* W_n      = (const float*)d_in[11];
    const float* b_n      = (const float*)d_in[12];

    float* h_out   = (float*)d_out;                          // [B, OUT]
    float* pot_out = (float*)d_out + (size_t)BATCH * DOUT;   // [B, 2*OUT]

    dim3 block(NTHREADS);
    dim3 grid1(D2 / BN, BATCH / BM);    // 16 x 32
    dim3 grid2(D2 / BN, BATCH / BM);    // 16 x 32 (z | r)
    dim3 grid3(DOUT / BN, BATCH / BM);  // 8 x 32

    k1_input_gemm<<<grid1, block>>>(x, h_prev, pot_prev, W_in, b_in, tresh, decay, pot_out);
    k2_zr_gemm<<<grid2, block>>>(h_prev, W_z, b_z, W_r, b_r);
    k3_cand_gemm<<<grid3, block>>>(h_prev, W_n, b_n, h_out);
}

// round 9
// speedup vs baseline: 1.5756x; 1.5756x over previous
#include <cuda_runtime.h>
#include <cuda_bf16.h>
#include <stdint.h>
#include <math.h>

#define BATCH 4096
#define DOUT  1024
#define D2    2048
#define D3    3072
#define K1    2048
#define K23   3072

#define BK     32
#define LDS    40                    // padded smem row (bf16 elements)
#define ATILEB (128*LDS*2)           // one 128xBK bf16 tile, bytes (10240)
#define STAGES 3
#define SMEM2 (STAGES*4*ATILEB)      // 2-way: 4 tiles/stage  -> 122880 B
#define SMEM3 (STAGES*6*ATILEB)      // 3-way: 6 tiles/stage  -> 184320 B

// ---- scratch (__device__ globals; allocation-free) ----
__device__ __nv_bfloat16 g_A1h0[(size_t)BATCH*K1];
__device__ __nv_bfloat16 g_A1h1[(size_t)BATCH*K1];
__device__ __nv_bfloat16 g_A1h2[(size_t)BATCH*K1];
__device__ __nv_bfloat16 g_A2hi[(size_t)BATCH*K23];
__device__ __nv_bfloat16 g_A2lo[(size_t)BATCH*K23];
__device__ __nv_bfloat16 g_A3hi[(size_t)BATCH*K23];
__device__ __nv_bfloat16 g_A3lo[(size_t)BATCH*K23];
__device__ __nv_bfloat16 g_B1h0[(size_t)D2*K1];
__device__ __nv_bfloat16 g_B1h1[(size_t)D2*K1];
__device__ __nv_bfloat16 g_B1h2[(size_t)D2*K1];
__device__ __nv_bfloat16 g_Bzhi[(size_t)DOUT*K23];
__device__ __nv_bfloat16 g_Bzlo[(size_t)DOUT*K23];
__device__ __nv_bfloat16 g_Brhi[(size_t)DOUT*K23];
__device__ __nv_bfloat16 g_Brlo[(size_t)DOUT*K23];
__device__ __nv_bfloat16 g_Bnhi[(size_t)DOUT*K23];
__device__ __nv_bfloat16 g_Bnlo[(size_t)DOUT*K23];
__device__ float g_z[(size_t)BATCH*DOUT];

// ---- helpers ----
__device__ __forceinline__ uint32_t s2u(const void* p){
    uint32_t r;
    asm("{ .reg .u64 t; cvta.to.shared.u64 t, %1; cvt.u32.u64 %0, t; }" : "=r"(r) : "l"(p));
    return r;
}
__device__ __forceinline__ void cp16(uint32_t dst, const void* src){
    asm volatile("cp.async.cg.shared.global [%0], [%1], 16;" :: "r"(dst), "l"(src));
}
__device__ __forceinline__ void ldm4(uint32_t* r, uint32_t a){
    asm volatile("ldmatrix.sync.aligned.m8n8.x4.shared.b16 {%0,%1,%2,%3}, [%4];"
                 : "=r"(r[0]),"=r"(r[1]),"=r"(r[2]),"=r"(r[3]) : "r"(a));
}
__device__ __forceinline__ void mma16816(float* d, const uint32_t* a, uint32_t b0, uint32_t b1){
    asm volatile("mma.sync.aligned.m16n8k16.row.col.f32.bf16.bf16.f32 "
                 "{%0,%1,%2,%3}, {%4,%5,%6,%7}, {%8,%9}, {%0,%1,%2,%3};"
                 : "+f"(d[0]),"+f"(d[1]),"+f"(d[2]),"+f"(d[3])
                 : "r"(a[0]),"r"(a[1]),"r"(a[2]),"r"(a[3]), "r"(b0),"r"(b1));
}
__device__ __forceinline__ void split2(float v, __nv_bfloat16& h, __nv_bfloat16& l){
    h = __float2bfloat16(v);
    l = __float2bfloat16(v - __bfloat162float(h));
}
__device__ __forceinline__ void split3(float v, __nv_bfloat16& h0, __nv_bfloat16& h1,
                                       __nv_bfloat16& h2){
    h0 = __float2bfloat16(v);
    float r = v - __bfloat162float(h0);
    h1 = __float2bfloat16(r);
    h2 = __float2bfloat16(r - __bfloat162float(h1));
}

// ---- mainloop template: NS-way split, passes ia+ib <= NS-1 ordered small->big.
// DRAIN=1: zero a temp accumulator every kk (K=16) and drain to master with RN
// adds, defeating the tensor-core's round-toward-zero accumulation bias. ----
template<int NS, int DRAIN>
__device__ __forceinline__ void gemm_mma(char* smem,
    const __nv_bfloat16* const* As, int ldA,
    const __nv_bfloat16* const* Bs, int ldB,
    int m0, int n0, int nch, float acc[4][4][4])
{
    const int tid = threadIdx.x, lane = tid & 31, wid = tid >> 5;
    const int warpm = wid >> 2, warpn = wid & 3;     // 2 x 4 warp grid
    const uint32_t sb = s2u(smem);
    const int NT = 2*NS;                             // tiles per stage
    const uint32_t stageb = NT*ATILEB;

    #pragma unroll
    for (int i = 0; i < 4; i++)
        #pragma unroll
        for (int j = 0; j < 4; j++)
            #pragma unroll
            for (int q = 0; q < 4; q++) acc[i][j][q] = 0.f;

    // prologue
    #pragma unroll
    for (int c = 0; c < STAGES-1; c++){
        uint32_t st = sb + c*stageb;
        int kt = c * BK;
        #pragma unroll
        for (int t = 0; t < NT; t++){
            const __nv_bfloat16* src = (t < NS) ? As[t] : Bs[t-NS];
            int base = (t < NS) ? m0 : n0;
            int ld   = (t < NS) ? ldA : ldB;
            #pragma unroll
            for (int i = 0; i < 2; i++){
                int idx = tid + (i << 8);
                int row = idx >> 2, g = idx & 3;
                uint32_t off = (uint32_t)(row*LDS + g*8)*2;
                cp16(st + t*ATILEB + off, src + (size_t)(base+row)*ld + kt + g*8);
            }
        }
        asm volatile("cp.async.commit_group;");
    }

    for (int c = 0; c < nch; c++){
        asm volatile("cp.async.wait_group %0;" :: "n"(STAGES-2));
        __syncthreads();
        if (c + STAGES-1 < nch){
            uint32_t st = sb + ((c + STAGES-1) % STAGES)*stageb;
            int kt = (c + STAGES-1) * BK;
            #pragma unroll
            for (int t = 0; t < NT; t++){
                const __nv_bfloat16* src = (t < NS) ? As[t] : Bs[t-NS];
                int base = (t < NS) ? m0 : n0;
                int ld   = (t < NS) ? ldA : ldB;
                #pragma unroll
                for (int i = 0; i < 2; i++){
                    int idx = tid + (i << 8);
                    int row = idx >> 2, g = idx & 3;
                    uint32_t off = (uint32_t)(row*LDS + g*8)*2;
                    cp16(st + t*ATILEB + off, src + (size_t)(base+row)*ld + kt + g*8);
                }
            }
            asm volatile("cp.async.commit_group;");
        }
        uint32_t st = sb + (c % STAGES)*stageb;
        #pragma unroll
        for (int kk = 0; kk < 2; kk++){
            uint32_t af[NS][4][4], bf[NS][2][4];
            #pragma unroll
            for (int s = 0; s < NS; s++){
                #pragma unroll
                for (int mt = 0; mt < 4; mt++){
                    uint32_t a = st + s*ATILEB + (uint32_t)(((warpm*64 + mt*16 + (lane & 15))*LDS
                                  + kk*16 + (lane >> 4)*8) * 2);
                    ldm4(af[s][mt], a);
                }
                #pragma unroll
                for (int p = 0; p < 2; p++){
                    uint32_t a = st + (NS+s)*ATILEB + (uint32_t)(((warpn*32 + p*16 + (lane & 15))*LDS
                                  + kk*16 + (lane >> 4)*8) * 2);
                    ldm4(bf[s][p], a);
                }
            }
            if (DRAIN){
                float tacc[4][4][4];
                #pragma unroll
                for (int i = 0; i < 4; i++)
                    #pragma unroll
                    for (int j = 0; j < 4; j++)
                        #pragma unroll
                        for (int q = 0; q < 4; q++) tacc[i][j][q] = 0.f;
                // small terms first, big (0,0) last: RZ roundings at full
                // magnitude are minimized
                #pragma unroll
                for (int sum = NS-1; sum >= 0; sum--)
                    #pragma unroll
                    for (int ia = 0; ia <= sum; ia++){
                        int ib = sum - ia;
                        #pragma unroll
                        for (int mt = 0; mt < 4; mt++)
                            #pragma unroll
                            for (int nt = 0; nt < 4; nt++){
                                int p = nt >> 1, o = nt & 1;
                                mma16816(tacc[mt][nt], af[ia][mt], bf[ib][p][o], bf[ib][p][o+2]);
                            }
                    }
                #pragma unroll
                for (int i = 0; i < 4; i++)
                    #pragma unroll
                    for (int j = 0; j < 4; j++)
                        #pragma unroll
                        for (int q = 0; q < 4; q++) acc[i][j][q] += tacc[i][j][q];
            } else {
                #pragma unroll
                for (int sum = NS-1; sum >= 0; sum--)
                    #pragma unroll
                    for (int ia = 0; ia <= sum; ia++){
                        int ib = sum - ia;
                        #pragma unroll
                        for (int mt = 0; mt < 4; mt++)
                            #pragma unroll
                            for (int nt = 0; nt < 4; nt++){
                                int p = nt >> 1, o = nt & 1;
                                mma16816(acc[mt][nt], af[ia][mt], bf[ib][p][o], bf[ib][p][o+2]);
                            }
                    }
            }
        }
    }
    asm volatile("cp.async.wait_group 0;");
}

// ---- kernel 1: input GEMM (3-way split, RZ-drained) + spike epilogue ----
__global__ void __launch_bounds__(256, 1)
k1_gemm(const float* __restrict__ pot_prev, const float* __restrict__ b_in,
        const float* __restrict__ tresh, const float* __restrict__ decay,
        float* __restrict__ pot_out)
{
    extern __shared__ char smem[];
    const int m0 = blockIdx.y * 128, n0 = blockIdx.x * 128;
    const __nv_bfloat16* As[3] = {g_A1h0, g_A1h1, g_A1h2};
    const __nv_bfloat16* Bs[3] = {g_B1h0, g_B1h1, g_B1h2};
    float acc[4][4][4];
    gemm_mma<3,1>(smem, As, K1, Bs, K1, m0, n0, K1/BK, acc);

    const int lane = threadIdx.x & 31, wid = threadIdx.x >> 5;
    const int warpm = wid >> 2, warpn = wid & 3;
    const int lrow = lane >> 2, lcol = (lane & 3)*2;
    #pragma unroll
    for (int mt = 0; mt < 4; mt++)
        #pragma unroll
        for (int nt = 0; nt < 4; nt++){
            int n = n0 + warpn*32 + nt*8 + lcol;
            float2 bi = *(const float2*)(b_in  + n);
            float2 th = *(const float2*)(tresh + n);
            float2 dc = *(const float2*)(decay + n);
            #pragma unroll
            for (int rr = 0; rr < 2; rr++){
                int m = m0 + warpm*64 + mt*16 + lrow + rr*8;
                size_t po = (size_t)m * D2 + n;
                float2 pp = *(const float2*)(pot_prev + po);
                float p0 = pp.x + acc[mt][nt][rr*2+0] + bi.x;
                float p1 = pp.y + acc[mt][nt][rr*2+1] + bi.y;
                bool s0 = p0 > th.x, s1 = p1 > th.y;
                float a0 = s0 ? p0 : 0.f, a1 = s1 ? p1 : 0.f;
                float2 pv = make_float2(s0 ? 0.f : p0*dc.x, s1 ? 0.f : p1*dc.y);
                *(float2*)(pot_out + po) = pv;
                __nv_bfloat16 h0,l0,h1,l1;
                split2(a0,h0,l0); split2(a1,h1,l1);
                uint32_t hp = (uint32_t)__bfloat16_as_ushort(h0) |
                              ((uint32_t)__bfloat16_as_ushort(h1) << 16);
                uint32_t lp = (uint32_t)__bfloat16_as_ushort(l0) |
                              ((uint32_t)__bfloat16_as_ushort(l1) << 16);
                size_t ao = (size_t)m * D3 + n;
                *(uint32_t*)(g_A2hi + ao) = hp;
                *(uint32_t*)(g_A2lo + ao) = lp;
                *(uint32_t*)(g_A3hi + ao) = hp;
                *(uint32_t*)(g_A3lo + ao) = lp;
            }
        }
}

// ---- kernel 2: z / r gates (2-way split) ----
__global__ void __launch_bounds__(256, 1)
k2_gemm(const float* __restrict__ h_prev, const float* __restrict__ b_z,
        const float* __restrict__ b_r)
{
    extern __shared__ char smem[];
    const int m0 = blockIdx.y * 128;
    const bool isZ = (blockIdx.x < 8);
    const int n0 = (blockIdx.x & 7) * 128;
    const __nv_bfloat16* As[2] = {g_A2hi, g_A2lo};
    const __nv_bfloat16* Bs[2] = {isZ ? g_Bzhi : g_Brhi, isZ ? g_Bzlo : g_Brlo};
    const float* bb = isZ ? b_z : b_r;
    float acc[4][4][4];
    gemm_mma<2,0>(smem, As, K23, Bs, K23, m0, n0, K23/BK, acc);

    const int lane = threadIdx.x & 31, wid = threadIdx.x >> 5;
    const int warpm = wid >> 2, warpn = wid & 3;
    const int lrow = lane >> 2, lcol = (lane & 3)*2;
    #pragma unroll
    for (int mt = 0; mt < 4; mt++)
        #pragma unroll
        for (int nt = 0; nt < 4; nt++){
            int n = n0 + warpn*32 + nt*8 + lcol;
            float2 bi = *(const float2*)(bb + n);
            #pragma unroll
            for (int rr = 0; rr < 2; rr++){
                int m = m0 + warpm*64 + mt*16 + lrow + rr*8;
                size_t ho = (size_t)m * DOUT + n;
                float v0 = acc[mt][nt][rr*2+0] + bi.x;
                float v1 = acc[mt][nt][rr*2+1] + bi.y;
                float s0 = 1.f / (1.f + __expf(-v0));
                float s1 = 1.f / (1.f + __expf(-v1));
                if (isZ){
                    *(float2*)(g_z + ho) = make_float2(s0, s1);
                } else {
                    float2 hh = *(const float2*)(h_prev + ho);
                    __nv_bfloat16 h0,l0,h1,l1;
                    split2(s0*hh.x, h0, l0);
                    split2(s1*hh.y, h1, l1);
                    uint32_t hp = (uint32_t)__bfloat16_as_ushort(h0) |
                                  ((uint32_t)__bfloat16_as_ushort(h1) << 16);
                    uint32_t lp = (uint32_t)__bfloat16_as_ushort(l0) |
                                  ((uint32_t)__bfloat16_as_ushort(l1) << 16);
                    size_t ao = (size_t)m * D3 + D2 + n;
                    *(uint32_t*)(g_A3hi + ao) = hp;
                    *(uint32_t*)(g_A3lo + ao) = lp;
                }
            }
        }
}

// ---- kernel 3: candidate + blend (2-way split) ----
__global__ void __launch_bounds__(256, 1)
k3_gemm(const float* __restrict__ h_prev, const float* __restrict__ b_n,
        float* __restrict__ h_out)
{
    extern __shared__ char smem[];
    const int m0 = blockIdx.y * 128, n0 = blockIdx.x * 128;
    const __nv_bfloat16* As[2] = {g_A3hi, g_A3lo};
    const __nv_bfloat16* Bs[2] = {g_Bnhi, g_Bnlo};
    float acc[4][4][4];
    gemm_mma<2,0>(smem, As, K23, Bs, K23, m0, n0, K23/BK, acc);

    const int lane = threadIdx.x & 31, wid = threadIdx.x >> 5;
    const int warpm = wid >> 2, warpn = wid & 3;
    const int lrow = lane >> 2, lcol = (lane & 3)*2;
    #pragma unroll
    for (int mt = 0; mt < 4; mt++)
        #pragma unroll
        for (int nt = 0; nt < 4; nt++){
            int n = n0 + warpn*32 + nt*8 + lcol;
            float2 bi = *(const float2*)(b_n + n);
            #pragma unroll
            for (int rr = 0; rr < 2; rr++){
                int m = m0 + warpm*64 + mt*16 + lrow + rr*8;
                size_t ho = (size_t)m * DOUT + n;
                float2 hh = *(const float2*)(h_prev + ho);
                float2 zz = *(const float2*)(g_z + ho);
                float n0v = tanhf(acc[mt][nt][rr*2+0] + bi.x);
                float n1v = tanhf(acc[mt][nt][rr*2+1] + bi.y);
                float2 ov = make_float2(hh.x + zz.x*(n0v - hh.x),
                                        hh.y + zz.y*(n1v - hh.y));
                *(float2*)(h_out + ho) = ov;
            }
        }
}

// ---- prep: split x (3-way) and h_prev (3-way for k1, 2-way for k2) ----
__global__ void __launch_bounds__(256)
prep_inputs(const float* __restrict__ x, const float* __restrict__ h)
{
    int i = blockIdx.x * 256 + threadIdx.x;
    int m = i >> 8, c4 = (i & 255) << 2;
    size_t so = (size_t)m*1024 + c4;
    float4 xv = *(const float4*)(x + so);
    float4 hv = *(const float4*)(h + so);
    float xa[4] = {xv.x,xv.y,xv.z,xv.w};
    float ha[4] = {hv.x,hv.y,hv.z,hv.w};
    __align__(8) __nv_bfloat16 x0[4],x1[4],x2[4],h0[4],h1[4],h2[4];
    #pragma unroll
    for (int j = 0; j < 4; j++){
        split3(xa[j], x0[j], x1[j], x2[j]);
        split3(ha[j], h0[j], h1[j], h2[j]);
    }
    size_t o1 = (size_t)m*K1 + c4;
    *(uint2*)(g_A1h0 + o1) = *(uint2*)x0;
    *(uint2*)(g_A1h1 + o1) = *(uint2*)x1;
    *(uint2*)(g_A1h2 + o1) = *(uint2*)x2;
    *(uint2*)(g_A1h0 + o1 + 1024) = *(uint2*)h0;
    *(uint2*)(g_A1h1 + o1 + 1024) = *(uint2*)h1;
    *(uint2*)(g_A1h2 + o1 + 1024) = *(uint2*)h2;
    __align__(8) __nv_bfloat16 hh[4], hl[4];
    #pragma unroll
    for (int j = 0; j < 4; j++) split2(ha[j], hh[j], hl[j]);
    size_t o2 = (size_t)m*K23 + D2 + c4;
    *(uint2*)(g_A2hi + o2) = *(uint2*)hh;
    *(uint2*)(g_A2lo + o2) = *(uint2*)hl;
}

// ---- prep: transpose + split weights W[K,N] fp32 -> [N,K] bf16 ----
__global__ void __launch_bounds__(256)
transpose_split(const float* __restrict__ W, int K, int N, int which)
{
    __shared__ float t[32][33];
    int n0 = blockIdx.x * 32, k0 = blockIdx.y * 32;
    int tx = threadIdx.x & 31, ty = threadIdx.x >> 5;
    #pragma unroll
    for (int i = 0; i < 32; i += 8)
        t[ty + i][tx] = W[(size_t)(k0 + ty + i)*N + n0 + tx];
    __syncthreads();
    #pragma unroll
    for (int i = 0; i < 32; i += 8){
        int n = n0 + ty + i, k = k0 + tx;
        size_t o = (size_t)n*K + k;
        float v = t[tx][ty + i];
        if (which == 0){
            __nv_bfloat16 h0,h1,h2;
            split3(v, h0, h1, h2);
            g_B1h0[o] = h0; g_B1h1[o] = h1; g_B1h2[o] = h2;
        } else {
            __nv_bfloat16 h, l;
            split2(v, h, l);
            if      (which == 1){ g_Bzhi[o] = h; g_Bzlo[o] = l; }
            else if (which == 2){ g_Brhi[o] = h; g_Brlo[o] = l; }
            else                { g_Bnhi[o] = h; g_Bnlo[o] = l; }
        }
    }
}

// ---- launch ----
extern "C" void kernel_launch(void* const* d_in, const int* in_sizes, int n_in,
                              void* d_out, int out_size)
{
    const float* x        = (const float*)d_in[0];
    const float* h_prev   = (const float*)d_in[1];
    const float* pot_prev = (const float*)d_in[2];
    const float* W_in     = (const float*)d_in[3];
    const float* b_in     = (const float*)d_in[4];
    const float* tresh    = (const float*)d_in[5];
    const float* decay    = (const float*)d_in[6];
    const float* W_z      = (const float*)d_in[7];
    const float* b_z      = (const float*)d_in[8];
    const float* W_r      = (const float*)d_in[9];
    const float* b_r      = (const float*)d_in[10];
    const float* W_n      = (const float*)d_in[11];
    const float* b_n      = (const float*)d_in[12];

    float* h_out   = (float*)d_out;
    float* pot_out = (float*)d_out + (size_t)BATCH * DOUT;

    cudaFuncSetAttribute(k1_gemm, cudaFuncAttributeMaxDynamicSharedMemorySize, SMEM3);
    cudaFuncSetAttribute(k2_gemm, cudaFuncAttributeMaxDynamicSharedMemorySize, SMEM2);
    cudaFuncSetAttribute(k3_gemm, cudaFuncAttributeMaxDynamicSharedMemorySize, SMEM2);

    prep_inputs<<<(BATCH*1024/4)/256, 256>>>(x, h_prev);
    transpose_split<<<dim3(D2/32,   K1/32),  256>>>(W_in, K1,  D2,   0);
    transpose_split<<<dim3(DOUT/32, K23/32), 256>>>(W_z,  K23, DOUT, 1);
    transpose_split<<<dim3(DOUT/32, K23/32), 256>>>(W_r,  K23, DOUT, 2);
    transpose_split<<<dim3(DOUT/32, K23/32), 256>>>(W_n,  K23, DOUT, 3);

    k1_gemm<<<dim3(16, 32), 256, SMEM3>>>(pot_prev, b_in, tresh, decay, pot_out);
    k2_gemm<<<dim3(16, 32), 256, SMEM2>>>(h_prev, b_z, b_r);
    k3_gemm<<<dim3(8,  32), 256, SMEM2>>>(h_prev, b_n, h_out);
}

// round 10
// speedup vs baseline: 2.4633x; 1.5634x over previous
#include <cuda_runtime.h>
#include <cuda_bf16.h>
#include <stdint.h>
#include <math.h>

#define BATCH 4096
#define DOUT  1024
#define D2    2048
#define D3    3072
#define K1    2048
#define K23   3072

#define BK     32
#define LDS    40                    // padded smem row (bf16 elements)
#define ATILEB (128*LDS*2)           // one 128xBK bf16 tile, bytes (10240)
#define STAGES 3
#define SMEM2 (STAGES*4*ATILEB)      // 2-way: 4 tiles/stage  -> 122880 B
#define SMEM3 (STAGES*6*ATILEB)      // 3-way: 6 tiles/stage  -> 184320 B

// ---- scratch (__device__ globals; allocation-free) ----
__device__ __nv_bfloat16 g_A1h0[(size_t)BATCH*K1];
__device__ __nv_bfloat16 g_A1h1[(size_t)BATCH*K1];
__device__ __nv_bfloat16 g_A1h2[(size_t)BATCH*K1];
__device__ __nv_bfloat16 g_A2hi[(size_t)BATCH*K23];
__device__ __nv_bfloat16 g_A2lo[(size_t)BATCH*K23];
__device__ __nv_bfloat16 g_A3hi[(size_t)BATCH*K23];
__device__ __nv_bfloat16 g_A3lo[(size_t)BATCH*K23];
__device__ __nv_bfloat16 g_B1h0[(size_t)D2*K1];
__device__ __nv_bfloat16 g_B1h1[(size_t)D2*K1];
__device__ __nv_bfloat16 g_B1h2[(size_t)D2*K1];
__device__ __nv_bfloat16 g_Bzhi[(size_t)DOUT*K23];
__device__ __nv_bfloat16 g_Bzlo[(size_t)DOUT*K23];
__device__ __nv_bfloat16 g_Brhi[(size_t)DOUT*K23];
__device__ __nv_bfloat16 g_Brlo[(size_t)DOUT*K23];
__device__ __nv_bfloat16 g_Bnhi[(size_t)DOUT*K23];
__device__ __nv_bfloat16 g_Bnlo[(size_t)DOUT*K23];
__device__ float g_z[(size_t)BATCH*DOUT];

// ---- helpers ----
__device__ __forceinline__ uint32_t s2u(const void* p){
    uint32_t r;
    asm("{ .reg .u64 t; cvta.to.shared.u64 t, %1; cvt.u32.u64 %0, t; }" : "=r"(r) : "l"(p));
    return r;
}
__device__ __forceinline__ void cp16(uint32_t dst, const void* src){
    asm volatile("cp.async.cg.shared.global [%0], [%1], 16;" :: "r"(dst), "l"(src));
}
__device__ __forceinline__ void ldm4(uint32_t* r, uint32_t a){
    asm volatile("ldmatrix.sync.aligned.m8n8.x4.shared.b16 {%0,%1,%2,%3}, [%4];"
                 : "=r"(r[0]),"=r"(r[1]),"=r"(r[2]),"=r"(r[3]) : "r"(a));
}
__device__ __forceinline__ void mma16816(float* d, const uint32_t* a, uint32_t b0, uint32_t b1){
    asm volatile("mma.sync.aligned.m16n8k16.row.col.f32.bf16.bf16.f32 "
                 "{%0,%1,%2,%3}, {%4,%5,%6,%7}, {%8,%9}, {%0,%1,%2,%3};"
                 : "+f"(d[0]),"+f"(d[1]),"+f"(d[2]),"+f"(d[3])
                 : "r"(a[0]),"r"(a[1]),"r"(a[2]),"r"(a[3]), "r"(b0),"r"(b1));
}
__device__ __forceinline__ void split2(float v, __nv_bfloat16& h, __nv_bfloat16& l){
    h = __float2bfloat16(v);
    l = __float2bfloat16(v - __bfloat162float(h));
}
__device__ __forceinline__ void split3(float v, __nv_bfloat16& h0, __nv_bfloat16& h1,
                                       __nv_bfloat16& h2){
    h0 = __float2bfloat16(v);
    float r = v - __bfloat162float(h0);
    h1 = __float2bfloat16(r);
    h2 = __float2bfloat16(r - __bfloat162float(h1));
}

// ---- mainloop template: NS-way split, passes ia+ib <= NS-1 ordered small->big.
// DRAIN=1: per-mt temp accumulator zeroed every kk, drained to master with RN
// adds (defeats tensor-core RZ accumulation bias) using only 16 temp regs. ----
template<int NS, int DRAIN>
__device__ __forceinline__ void gemm_mma(char* smem,
    const __nv_bfloat16* const* As, int ldA,
    const __nv_bfloat16* const* Bs, int ldB,
    int m0, int n0, int nch, float acc[4][4][4])
{
    const int tid = threadIdx.x, lane = tid & 31, wid = tid >> 5;
    const int warpm = wid >> 2, warpn = wid & 3;     // 2 x 4 warp grid
    const uint32_t sb = s2u(smem);
    const int NT = 2*NS;                             // tiles per stage
    const uint32_t stageb = NT*ATILEB;

    #pragma unroll
    for (int i = 0; i < 4; i++)
        #pragma unroll
        for (int j = 0; j < 4; j++)
            #pragma unroll
            for (int q = 0; q < 4; q++) acc[i][j][q] = 0.f;

    // prologue
    #pragma unroll
    for (int c = 0; c < STAGES-1; c++){
        uint32_t st = sb + c*stageb;
        int kt = c * BK;
        #pragma unroll
        for (int t = 0; t < NT; t++){
            const __nv_bfloat16* src = (t < NS) ? As[t] : Bs[t-NS];
            int base = (t < NS) ? m0 : n0;
            int ld   = (t < NS) ? ldA : ldB;
            #pragma unroll
            for (int i = 0; i < 2; i++){
                int idx = tid + (i << 8);
                int row = idx >> 2, g = idx & 3;
                uint32_t off = (uint32_t)(row*LDS + g*8)*2;
                cp16(st + t*ATILEB + off, src + (size_t)(base+row)*ld + kt + g*8);
            }
        }
        asm volatile("cp.async.commit_group;");
    }

    for (int c = 0; c < nch; c++){
        asm volatile("cp.async.wait_group %0;" :: "n"(STAGES-2));
        __syncthreads();
        if (c + STAGES-1 < nch){
            uint32_t st = sb + ((c + STAGES-1) % STAGES)*stageb;
            int kt = (c + STAGES-1) * BK;
            #pragma unroll
            for (int t = 0; t < NT; t++){
                const __nv_bfloat16* src = (t < NS) ? As[t] : Bs[t-NS];
                int base = (t < NS) ? m0 : n0;
                int ld   = (t < NS) ? ldA : ldB;
                #pragma unroll
                for (int i = 0; i < 2; i++){
                    int idx = tid + (i << 8);
                    int row = idx >> 2, g = idx & 3;
                    uint32_t off = (uint32_t)(row*LDS + g*8)*2;
                    cp16(st + t*ATILEB + off, src + (size_t)(base+row)*ld + kt + g*8);
                }
            }
            asm volatile("cp.async.commit_group;");
        }
        uint32_t st = sb + (c % STAGES)*stageb;
        #pragma unroll
        for (int kk = 0; kk < 2; kk++){
            uint32_t af[NS][4][4], bf[NS][2][4];
            #pragma unroll
            for (int s = 0; s < NS; s++){
                #pragma unroll
                for (int mt = 0; mt < 4; mt++){
                    uint32_t a = st + s*ATILEB + (uint32_t)(((warpm*64 + mt*16 + (lane & 15))*LDS
                                  + kk*16 + (lane >> 4)*8) * 2);
                    ldm4(af[s][mt], a);
                }
                #pragma unroll
                for (int p = 0; p < 2; p++){
                    uint32_t a = st + (NS+s)*ATILEB + (uint32_t)(((warpn*32 + p*16 + (lane & 15))*LDS
                                  + kk*16 + (lane >> 4)*8) * 2);
                    ldm4(bf[s][p], a);
                }
            }
            if (DRAIN){
                // per-mt temp accumulator: only 16 extra registers
                #pragma unroll
                for (int mt = 0; mt < 4; mt++){
                    float tacc[4][4];
                    #pragma unroll
                    for (int j = 0; j < 4; j++)
                        #pragma unroll
                        for (int q = 0; q < 4; q++) tacc[j][q] = 0.f;
                    #pragma unroll
                    for (int sum = NS-1; sum >= 0; sum--)
                        #pragma unroll
                        for (int ia = 0; ia <= sum; ia++){
                            int ib = sum - ia;
                            #pragma unroll
                            for (int nt = 0; nt < 4; nt++){
                                int p = nt >> 1, o = nt & 1;
                                mma16816(tacc[nt], af[ia][mt], bf[ib][p][o], bf[ib][p][o+2]);
                            }
                        }
                    #pragma unroll
                    for (int j = 0; j < 4; j++)
                        #pragma unroll
                        for (int q = 0; q < 4; q++) acc[mt][j][q] += tacc[j][q];
                }
            } else {
                #pragma unroll
                for (int sum = NS-1; sum >= 0; sum--)
                    #pragma unroll
                    for (int ia = 0; ia <= sum; ia++){
                        int ib = sum - ia;
                        #pragma unroll
                        for (int mt = 0; mt < 4; mt++)
                            #pragma unroll
                            for (int nt = 0; nt < 4; nt++){
                                int p = nt >> 1, o = nt & 1;
                                mma16816(acc[mt][nt], af[ia][mt], bf[ib][p][o], bf[ib][p][o+2]);
                            }
                    }
            }
        }
    }
    asm volatile("cp.async.wait_group 0;");
}

// ---- kernel 1: input GEMM (3-way split, RZ-drained) + spike epilogue ----
__global__ void __launch_bounds__(256, 1)
k1_gemm(const float* __restrict__ pot_prev, const float* __restrict__ b_in,
        const float* __restrict__ tresh, const float* __restrict__ decay,
        float* __restrict__ pot_out)
{
    extern __shared__ char smem[];
    const int m0 = blockIdx.y * 128, n0 = blockIdx.x * 128;
    const __nv_bfloat16* As[3] = {g_A1h0, g_A1h1, g_A1h2};
    const __nv_bfloat16* Bs[3] = {g_B1h0, g_B1h1, g_B1h2};
    float acc[4][4][4];
    gemm_mma<3,1>(smem, As, K1, Bs, K1, m0, n0, K1/BK, acc);

    const int lane = threadIdx.x & 31, wid = threadIdx.x >> 5;
    const int warpm = wid >> 2, warpn = wid & 3;
    const int lrow = lane >> 2, lcol = (lane & 3)*2;
    #pragma unroll
    for (int mt = 0; mt < 4; mt++)
        #pragma unroll
        for (int nt = 0; nt < 4; nt++){
            int n = n0 + warpn*32 + nt*8 + lcol;
            float2 bi = *(const float2*)(b_in  + n);
            float2 th = *(const float2*)(tresh + n);
            float2 dc = *(const float2*)(decay + n);
            #pragma unroll
            for (int rr = 0; rr < 2; rr++){
                int m = m0 + warpm*64 + mt*16 + lrow + rr*8;
                size_t po = (size_t)m * D2 + n;
                float2 pp = *(const float2*)(pot_prev + po);
                float p0 = pp.x + acc[mt][nt][rr*2+0] + bi.x;
                float p1 = pp.y + acc[mt][nt][rr*2+1] + bi.y;
                bool s0 = p0 > th.x, s1 = p1 > th.y;
                float a0 = s0 ? p0 : 0.f, a1 = s1 ? p1 : 0.f;
                float2 pv = make_float2(s0 ? 0.f : p0*dc.x, s1 ? 0.f : p1*dc.y);
                *(float2*)(pot_out + po) = pv;
                __nv_bfloat16 h0,l0,h1,l1;
                split2(a0,h0,l0); split2(a1,h1,l1);
                uint32_t hp = (uint32_t)__bfloat16_as_ushort(h0) |
                              ((uint32_t)__bfloat16_as_ushort(h1) << 16);
                uint32_t lp = (uint32_t)__bfloat16_as_ushort(l0) |
                              ((uint32_t)__bfloat16_as_ushort(l1) << 16);
                size_t ao = (size_t)m * D3 + n;
                *(uint32_t*)(g_A2hi + ao) = hp;
                *(uint32_t*)(g_A2lo + ao) = lp;
                *(uint32_t*)(g_A3hi + ao) = hp;
                *(uint32_t*)(g_A3lo + ao) = lp;
            }
        }
}

// ---- kernel 2: z / r gates (2-way split) ----
__global__ void __launch_bounds__(256, 1)
k2_gemm(const float* __restrict__ h_prev, const float* __restrict__ b_z,
        const float* __restrict__ b_r)
{
    extern __shared__ char smem[];
    const int m0 = blockIdx.y * 128;
    const bool isZ = (blockIdx.x < 8);
    const int n0 = (blockIdx.x & 7) * 128;
    const __nv_bfloat16* As[2] = {g_A2hi, g_A2lo};
    const __nv_bfloat16* Bs[2] = {isZ ? g_Bzhi : g_Brhi, isZ ? g_Bzlo : g_Brlo};
    const float* bb = isZ ? b_z : b_r;
    float acc[4][4][4];
    gemm_mma<2,0>(smem, As, K23, Bs, K23, m0, n0, K23/BK, acc);

    const int lane = threadIdx.x & 31, wid = threadIdx.x >> 5;
    const int warpm = wid >> 2, warpn = wid & 3;
    const int lrow = lane >> 2, lcol = (lane & 3)*2;
    #pragma unroll
    for (int mt = 0; mt < 4; mt++)
        #pragma unroll
        for (int nt = 0; nt < 4; nt++){
            int n = n0 + warpn*32 + nt*8 + lcol;
            float2 bi = *(const float2*)(bb + n);
            #pragma unroll
            for (int rr = 0; rr < 2; rr++){
                int m = m0 + warpm*64 + mt*16 + lrow + rr*8;
                size_t ho = (size_t)m * DOUT + n;
                float v0 = acc[mt][nt][rr*2+0] + bi.x;
                float v1 = acc[mt][nt][rr*2+1] + bi.y;
                float s0 = 1.f / (1.f + __expf(-v0));
                float s1 = 1.f / (1.f + __expf(-v1));
                if (isZ){
                    *(float2*)(g_z + ho) = make_float2(s0, s1);
                } else {
                    float2 hh = *(const float2*)(h_prev + ho);
                    __nv_bfloat16 h0,l0,h1,l1;
                    split2(s0*hh.x, h0, l0);
                    split2(s1*hh.y, h1, l1);
                    uint32_t hp = (uint32_t)__bfloat16_as_ushort(h0) |
                                  ((uint32_t)__bfloat16_as_ushort(h1) << 16);
                    uint32_t lp = (uint32_t)__bfloat16_as_ushort(l0) |
                                  ((uint32_t)__bfloat16_as_ushort(l1) << 16);
                    size_t ao = (size_t)m * D3 + D2 + n;
                    *(uint32_t*)(g_A3hi + ao) = hp;
                    *(uint32_t*)(g_A3lo + ao) = lp;
                }
            }
        }
}

// ---- kernel 3: candidate + blend (2-way split) ----
__global__ void __launch_bounds__(256, 1)
k3_gemm(const float* __restrict__ h_prev, const float* __restrict__ b_n,
        float* __restrict__ h_out)
{
    extern __shared__ char smem[];
    const int m0 = blockIdx.y * 128, n0 = blockIdx.x * 128;
    const __nv_bfloat16* As[2] = {g_A3hi, g_A3lo};
    const __nv_bfloat16* Bs[2] = {g_Bnhi, g_Bnlo};
    float acc[4][4][4];
    gemm_mma<2,0>(smem, As, K23, Bs, K23, m0, n0, K23/BK, acc);

    const int lane = threadIdx.x & 31, wid = threadIdx.x >> 5;
    const int warpm = wid >> 2, warpn = wid & 3;
    const int lrow = lane >> 2, lcol = (lane & 3)*2;
    #pragma unroll
    for (int mt = 0; mt < 4; mt++)
        #pragma unroll
        for (int nt = 0; nt < 4; nt++){
            int n = n0 + warpn*32 + nt*8 + lcol;
            float2 bi = *(const float2*)(b_n + n);
            #pragma unroll
            for (int rr = 0; rr < 2; rr++){
                int m = m0 + warpm*64 + mt*16 + lrow + rr*8;
                size_t ho = (size_t)m * DOUT + n;
                float2 hh = *(const float2*)(h_prev + ho);
                float2 zz = *(const float2*)(g_z + ho);
                float n0v = tanhf(acc[mt][nt][rr*2+0] + bi.x);
                float n1v = tanhf(acc[mt][nt][rr*2+1] + bi.y);
                float2 ov = make_float2(hh.x + zz.x*(n0v - hh.x),
                                        hh.y + zz.y*(n1v - hh.y));
                *(float2*)(h_out + ho) = ov;
            }
        }
}

// ---- prep: split x (3-way) and h_prev (3-way for k1, 2-way for k2) ----
__global__ void __launch_bounds__(256)
prep_inputs(const float* __restrict__ x, const float* __restrict__ h)
{
    int i = blockIdx.x * 256 + threadIdx.x;
    int m = i >> 8, c4 = (i & 255) << 2;
    size_t so = (size_t)m*1024 + c4;
    float4 xv = *(const float4*)(x + so);
    float4 hv = *(const float4*)(h + so);
    float xa[4] = {xv.x,xv.y,xv.z,xv.w};
    float ha[4] = {hv.x,hv.y,hv.z,hv.w};
    __align__(8) __nv_bfloat16 x0[4],x1[4],x2[4],h0[4],h1[4],h2[4];
    #pragma unroll
    for (int j = 0; j < 4; j++){
        split3(xa[j], x0[j], x1[j], x2[j]);
        split3(ha[j], h0[j], h1[j], h2[j]);
    }
    size_t o1 = (size_t)m*K1 + c4;
    *(uint2*)(g_A1h0 + o1) = *(uint2*)x0;
    *(uint2*)(g_A1h1 + o1) = *(uint2*)x1;
    *(uint2*)(g_A1h2 + o1) = *(uint2*)x2;
    *(uint2*)(g_A1h0 + o1 + 1024) = *(uint2*)h0;
    *(uint2*)(g_A1h1 + o1 + 1024) = *(uint2*)h1;
    *(uint2*)(g_A1h2 + o1 + 1024) = *(uint2*)h2;
    __align__(8) __nv_bfloat16 hh[4], hl[4];
    #pragma unroll
    for (int j = 0; j < 4; j++) split2(ha[j], hh[j], hl[j]);
    size_t o2 = (size_t)m*K23 + D2 + c4;
    *(uint2*)(g_A2hi + o2) = *(uint2*)hh;
    *(uint2*)(g_A2lo + o2) = *(uint2*)hl;
}

// ---- prep: transpose + split weights W[K,N] fp32 -> [N,K] bf16 ----
__global__ void __launch_bounds__(256)
transpose_split(const float* __restrict__ W, int K, int N, int which)
{
    __shared__ float t[32][33];
    int n0 = blockIdx.x * 32, k0 = blockIdx.y * 32;
    int tx = threadIdx.x & 31, ty = threadIdx.x >> 5;
    #pragma unroll
    for (int i = 0; i < 32; i += 8)
        t[ty + i][tx] = W[(size_t)(k0 + ty + i)*N + n0 + tx];
    __syncthreads();
    #pragma unroll
    for (int i = 0; i < 32; i += 8){
        int n = n0 + ty + i, k = k0 + tx;
        size_t o = (size_t)n*K + k;
        float v = t[tx][ty + i];
        if (which == 0){
            __nv_bfloat16 h0,h1,h2;
            split3(v, h0, h1, h2);
            g_B1h0[o] = h0; g_B1h1[o] = h1; g_B1h2[o] = h2;
        } else {
            __nv_bfloat16 h, l;
            split2(v, h, l);
            if      (which == 1){ g_Bzhi[o] = h; g_Bzlo[o] = l; }
            else if (which == 2){ g_Brhi[o] = h; g_Brlo[o] = l; }
            else                { g_Bnhi[o] = h; g_Bnlo[o] = l; }
        }
    }
}

// ---- launch ----
extern "C" void kernel_launch(void* const* d_in, const int* in_sizes, int n_in,
                              void* d_out, int out_size)
{
    const float* x        = (const float*)d_in[0];
    const float* h_prev   = (const float*)d_in[1];
    const float* pot_prev = (const float*)d_in[2];
    const float* W_in     = (const float*)d_in[3];
    const float* b_in     = (const float*)d_in[4];
    const float* tresh    = (const float*)d_in[5];
    const float* decay    = (const float*)d_in[6];
    const float* W_z      = (const float*)d_in[7];
    const float* b_z      = (const float*)d_in[8];
    const float* W_r      = (const float*)d_in[9];
    const float* b_r      = (const float*)d_in[10];
    const float* W_n      = (const float*)d_in[11];
    const float* b_n      = (const float*)d_in[12];

    float* h_out   = (float*)d_out;
    float* pot_out = (float*)d_out + (size_t)BATCH * DOUT;

    cudaFuncSetAttribute(k1_gemm, cudaFuncAttributeMaxDynamicSharedMemorySize, SMEM3);
    cudaFuncSetAttribute(k2_gemm, cudaFuncAttributeMaxDynamicSharedMemorySize, SMEM2);
    cudaFuncSetAttribute(k3_gemm, cudaFuncAttributeMaxDynamicSharedMemorySize, SMEM2);

    prep_inputs<<<(BATCH*1024/4)/256, 256>>>(x, h_prev);
    transpose_split<<<dim3(D2/32,   K1/32),  256>>>(W_in, K1,  D2,   0);
    transpose_split<<<dim3(DOUT/32, K23/32), 256>>>(W_z,  K23, DOUT, 1);
    transpose_split<<<dim3(DOUT/32, K23/32), 256>>>(W_r,  K23, DOUT, 2);
    transpose_split<<<dim3(DOUT/32, K23/32), 256>>>(W_n,  K23, DOUT, 3);

    k1_gemm<<<dim3(16, 32), 256, SMEM3>>>(pot_prev, b_in, tresh, decay, pot_out);
    k2_gemm<<<dim3(16, 32), 256, SMEM2>>>(h_prev, b_z, b_r);
    k3_gemm<<<dim3(8,  32), 256, SMEM2>>>(h_prev, b_n, h_out);
}

// round 11
// speedup vs baseline: 2.8738x; 1.1667x over previous
#include <cuda_runtime.h>
#include <cuda_bf16.h>
#include <stdint.h>
#include <math.h>

#define BATCH 4096
#define DOUT  1024
#define D2    2048
#define D3    3072
#define K1    2048
#define K23   3072

#define BK     32
#define LDS    40                    // padded smem row (bf16 elements)
#define ATILEB (128*LDS*2)           // one 128xBK bf16 tile, bytes (10240)
#define STAGES 3
#define SMEM2 (STAGES*4*ATILEB)      // 2-way: 4 tiles/stage -> 122880 B

#define MARGIN 5e-4f
#define FIXCAP (1<<20)

// ---- scratch (__device__ globals; allocation-free) ----
__device__ __nv_bfloat16 g_A1hi[(size_t)BATCH*K1];
__device__ __nv_bfloat16 g_A1lo[(size_t)BATCH*K1];
__device__ __nv_bfloat16 g_A2hi[(size_t)BATCH*K23];
__device__ __nv_bfloat16 g_A2lo[(size_t)BATCH*K23];
__device__ __nv_bfloat16 g_A3hi[(size_t)BATCH*K23];
__device__ __nv_bfloat16 g_A3lo[(size_t)BATCH*K23];
__device__ __nv_bfloat16 g_B1hi[(size_t)D2*K1];
__device__ __nv_bfloat16 g_B1lo[(size_t)D2*K1];
__device__ __nv_bfloat16 g_Bzhi[(size_t)DOUT*K23];
__device__ __nv_bfloat16 g_Bzlo[(size_t)DOUT*K23];
__device__ __nv_bfloat16 g_Brhi[(size_t)DOUT*K23];
__device__ __nv_bfloat16 g_Brlo[(size_t)DOUT*K23];
__device__ __nv_bfloat16 g_Bnhi[(size_t)DOUT*K23];
__device__ __nv_bfloat16 g_Bnlo[(size_t)DOUT*K23];
__device__ float g_z[(size_t)BATCH*DOUT];
__device__ uint32_t g_fix_list[FIXCAP];
__device__ uint32_t g_fix_count;

// ---- helpers ----
__device__ __forceinline__ uint32_t s2u(const void* p){
    uint32_t r;
    asm("{ .reg .u64 t; cvta.to.shared.u64 t, %1; cvt.u32.u64 %0, t; }" : "=r"(r) : "l"(p));
    return r;
}
__device__ __forceinline__ void cp16(uint32_t dst, const void* src){
    asm volatile("cp.async.cg.shared.global [%0], [%1], 16;" :: "r"(dst), "l"(src));
}
__device__ __forceinline__ void ldm4(uint32_t* r, uint32_t a){
    asm volatile("ldmatrix.sync.aligned.m8n8.x4.shared.b16 {%0,%1,%2,%3}, [%4];"
                 : "=r"(r[0]),"=r"(r[1]),"=r"(r[2]),"=r"(r[3]) : "r"(a));
}
__device__ __forceinline__ void mma16816(float* d, const uint32_t* a, uint32_t b0, uint32_t b1){
    asm volatile("mma.sync.aligned.m16n8k16.row.col.f32.bf16.bf16.f32 "
                 "{%0,%1,%2,%3}, {%4,%5,%6,%7}, {%8,%9}, {%0,%1,%2,%3};"
                 : "+f"(d[0]),"+f"(d[1]),"+f"(d[2]),"+f"(d[3])
                 : "r"(a[0]),"r"(a[1]),"r"(a[2]),"r"(a[3]), "r"(b0),"r"(b1));
}
__device__ __forceinline__ void split2(float v, __nv_bfloat16& h, __nv_bfloat16& l){
    h = __float2bfloat16(v);
    l = __float2bfloat16(v - __bfloat162float(h));
}

// ---- mainloop: 2-way split, 3 passes small->big.
// DRAIN=1: per-mt temp accumulator zeroed every kk, drained with RN adds
// (defeats tensor-core RZ accumulation bias). ----
template<int DRAIN>
__device__ __forceinline__ void gemm_mma(char* smem,
    const __nv_bfloat16* const* As, int ldA,
    const __nv_bfloat16* const* Bs, int ldB,
    int m0, int n0, int nch, float acc[4][4][4])
{
    const int NS = 2;
    const int tid = threadIdx.x, lane = tid & 31, wid = tid >> 5;
    const int warpm = wid >> 2, warpn = wid & 3;     // 2 x 4 warp grid
    const uint32_t sb = s2u(smem);
    const int NT = 2*NS;
    const uint32_t stageb = NT*ATILEB;

    #pragma unroll
    for (int i = 0; i < 4; i++)
        #pragma unroll
        for (int j = 0; j < 4; j++)
            #pragma unroll
            for (int q = 0; q < 4; q++) acc[i][j][q] = 0.f;

    #pragma unroll
    for (int c = 0; c < STAGES-1; c++){
        uint32_t st = sb + c*stageb;
        int kt = c * BK;
        #pragma unroll
        for (int t = 0; t < NT; t++){
            const __nv_bfloat16* src = (t < NS) ? As[t] : Bs[t-NS];
            int base = (t < NS) ? m0 : n0;
            int ld   = (t < NS) ? ldA : ldB;
            #pragma unroll
            for (int i = 0; i < 2; i++){
                int idx = tid + (i << 8);
                int row = idx >> 2, g = idx & 3;
                uint32_t off = (uint32_t)(row*LDS + g*8)*2;
                cp16(st + t*ATILEB + off, src + (size_t)(base+row)*ld + kt + g*8);
            }
        }
        asm volatile("cp.async.commit_group;");
    }

    for (int c = 0; c < nch; c++){
        asm volatile("cp.async.wait_group %0;" :: "n"(STAGES-2));
        __syncthreads();
        if (c + STAGES-1 < nch){
            uint32_t st = sb + ((c + STAGES-1) % STAGES)*stageb;
            int kt = (c + STAGES-1) * BK;
            #pragma unroll
            for (int t = 0; t < NT; t++){
                const __nv_bfloat16* src = (t < NS) ? As[t] : Bs[t-NS];
                int base = (t < NS) ? m0 : n0;
                int ld   = (t < NS) ? ldA : ldB;
                #pragma unroll
                for (int i = 0; i < 2; i++){
                    int idx = tid + (i << 8);
                    int row = idx >> 2, g = idx & 3;
                    uint32_t off = (uint32_t)(row*LDS + g*8)*2;
                    cp16(st + t*ATILEB + off, src + (size_t)(base+row)*ld + kt + g*8);
                }
            }
            asm volatile("cp.async.commit_group;");
        }
        uint32_t st = sb + (c % STAGES)*stageb;
        #pragma unroll
        for (int kk = 0; kk < 2; kk++){
            uint32_t af[NS][4][4], bf[NS][2][4];
            #pragma unroll
            for (int s = 0; s < NS; s++){
                #pragma unroll
                for (int mt = 0; mt < 4; mt++){
                    uint32_t a = st + s*ATILEB + (uint32_t)(((warpm*64 + mt*16 + (lane & 15))*LDS
                                  + kk*16 + (lane >> 4)*8) * 2);
                    ldm4(af[s][mt], a);
                }
                #pragma unroll
                for (int p = 0; p < 2; p++){
                    uint32_t a = st + (NS+s)*ATILEB + (uint32_t)(((warpn*32 + p*16 + (lane & 15))*LDS
                                  + kk*16 + (lane >> 4)*8) * 2);
                    ldm4(bf[s][p], a);
                }
            }
            if (DRAIN){
                #pragma unroll
                for (int mt = 0; mt < 4; mt++){
                    float tacc[4][4];
                    #pragma unroll
                    for (int j = 0; j < 4; j++)
                        #pragma unroll
                        for (int q = 0; q < 4; q++) tacc[j][q] = 0.f;
                    #pragma unroll
                    for (int sum = NS-1; sum >= 0; sum--)
                        #pragma unroll
                        for (int ia = 0; ia <= sum; ia++){
                            int ib = sum - ia;
                            #pragma unroll
                            for (int nt = 0; nt < 4; nt++){
                                int p = nt >> 1, o = nt & 1;
                                mma16816(tacc[nt], af[ia][mt], bf[ib][p][o], bf[ib][p][o+2]);
                            }
                        }
                    #pragma unroll
                    for (int j = 0; j < 4; j++)
                        #pragma unroll
                        for (int q = 0; q < 4; q++) acc[mt][j][q] += tacc[j][q];
                }
            } else {
                #pragma unroll
                for (int sum = NS-1; sum >= 0; sum--)
                    #pragma unroll
                    for (int ia = 0; ia <= sum; ia++){
                        int ib = sum - ia;
                        #pragma unroll
                        for (int mt = 0; mt < 4; mt++)
                            #pragma unroll
                            for (int nt = 0; nt < 4; nt++){
                                int p = nt >> 1, o = nt & 1;
                                mma16816(acc[mt][nt], af[ia][mt], bf[ib][p][o], bf[ib][p][o+2]);
                            }
                    }
            }
        }
    }
    asm volatile("cp.async.wait_group 0;");
}

// ---- kernel 1: input GEMM (2-way, drained) + spike epilogue + flag ----
__global__ void __launch_bounds__(256, 1)
k1_gemm(const float* __restrict__ pot_prev, const float* __restrict__ b_in,
        const float* __restrict__ tresh, const float* __restrict__ decay,
        float* __restrict__ pot_out)
{
    extern __shared__ char smem[];
    const int m0 = blockIdx.y * 128, n0 = blockIdx.x * 128;
    const __nv_bfloat16* As[2] = {g_A1hi, g_A1lo};
    const __nv_bfloat16* Bs[2] = {g_B1hi, g_B1lo};
    float acc[4][4][4];
    gemm_mma<1>(smem, As, K1, Bs, K1, m0, n0, K1/BK, acc);

    const int lane = threadIdx.x & 31, wid = threadIdx.x >> 5;
    const int warpm = wid >> 2, warpn = wid & 3;
    const int lrow = lane >> 2, lcol = (lane & 3)*2;
    #pragma unroll
    for (int mt = 0; mt < 4; mt++)
        #pragma unroll
        for (int nt = 0; nt < 4; nt++){
            int n = n0 + warpn*32 + nt*8 + lcol;
            float2 bi = *(const float2*)(b_in  + n);
            float2 th = *(const float2*)(tresh + n);
            float2 dc = *(const float2*)(decay + n);
            #pragma unroll
            for (int rr = 0; rr < 2; rr++){
                int m = m0 + warpm*64 + mt*16 + lrow + rr*8;
                size_t po = (size_t)m * D2 + n;
                float2 pp = *(const float2*)(pot_prev + po);
                float p0 = pp.x + acc[mt][nt][rr*2+0] + bi.x;
                float p1 = pp.y + acc[mt][nt][rr*2+1] + bi.y;
                // flag near-threshold elements for exact fp32 recompute
                if (fabsf(p0 - th.x) < MARGIN){
                    uint32_t ix = atomicAdd(&g_fix_count, 1u);
                    if (ix < FIXCAP) g_fix_list[ix] = ((uint32_t)m << 11) | (uint32_t)n;
                }
                if (fabsf(p1 - th.y) < MARGIN){
                    uint32_t ix = atomicAdd(&g_fix_count, 1u);
                    if (ix < FIXCAP) g_fix_list[ix] = ((uint32_t)m << 11) | (uint32_t)(n+1);
                }
                bool s0 = p0 > th.x, s1 = p1 > th.y;
                float a0 = s0 ? p0 : 0.f, a1 = s1 ? p1 : 0.f;
                float2 pv = make_float2(s0 ? 0.f : p0*dc.x, s1 ? 0.f : p1*dc.y);
                *(float2*)(pot_out + po) = pv;
                __nv_bfloat16 h0,l0,h1,l1;
                split2(a0,h0,l0); split2(a1,h1,l1);
                uint32_t hp = (uint32_t)__bfloat16_as_ushort(h0) |
                              ((uint32_t)__bfloat16_as_ushort(h1) << 16);
                uint32_t lp = (uint32_t)__bfloat16_as_ushort(l0) |
                              ((uint32_t)__bfloat16_as_ushort(l1) << 16);
                size_t ao = (size_t)m * D3 + n;
                *(uint32_t*)(g_A2hi + ao) = hp;
                *(uint32_t*)(g_A2lo + ao) = lp;
                *(uint32_t*)(g_A3hi + ao) = hp;
                *(uint32_t*)(g_A3lo + ao) = lp;
            }
        }
}

// ---- fixup: exact fp32 recompute of flagged elements, patch outputs ----
__global__ void __launch_bounds__(256)
k1_fixup(const float* __restrict__ x, const float* __restrict__ h,
         const float* __restrict__ pot_prev, const float* __restrict__ W_in,
         const float* __restrict__ b_in, const float* __restrict__ tresh,
         const float* __restrict__ decay, float* __restrict__ pot_out)
{
    int lane = threadIdx.x & 31;
    int warp = (blockIdx.x * blockDim.x + threadIdx.x) >> 5;
    int nwarps = (gridDim.x * blockDim.x) >> 5;
    uint32_t cnt = g_fix_count;
    if (cnt > FIXCAP) cnt = FIXCAP;
    for (uint32_t i = warp; i < cnt; i += nwarps){
        uint32_t mn = g_fix_list[i];
        int m = mn >> 11, n = mn & 2047;
        float s = 0.f;
        const float* xr = x + (size_t)m * 1024;
        const float* hr = h + (size_t)m * 1024;
        #pragma unroll 4
        for (int k = lane; k < 1024; k += 32)
            s = fmaf(xr[k], W_in[(size_t)k * D2 + n], s);
        #pragma unroll 4
        for (int k = lane; k < 1024; k += 32)
            s = fmaf(hr[k], W_in[(size_t)(k + 1024) * D2 + n], s);
        #pragma unroll
        for (int o = 16; o; o >>= 1) s += __shfl_xor_sync(0xFFFFFFFFu, s, o);
        if (lane == 0){
            float pt = pot_prev[(size_t)m * D2 + n] + s + b_in[n];
            bool spk = pt > tresh[n];
            float act = spk ? pt : 0.f;
            pot_out[(size_t)m * D2 + n] = spk ? 0.f : pt * decay[n];
            __nv_bfloat16 hh, ll;
            split2(act, hh, ll);
            size_t ao = (size_t)m * D3 + n;
            g_A2hi[ao] = hh; g_A2lo[ao] = ll;
            g_A3hi[ao] = hh; g_A3lo[ao] = ll;
        }
    }
}

// ---- kernel 2: z / r gates (2-way split) ----
__global__ void __launch_bounds__(256, 1)
k2_gemm(const float* __restrict__ h_prev, const float* __restrict__ b_z,
        const float* __restrict__ b_r)
{
    extern __shared__ char smem[];
    const int m0 = blockIdx.y * 128;
    const bool isZ = (blockIdx.x < 8);
    const int n0 = (blockIdx.x & 7) * 128;
    const __nv_bfloat16* As[2] = {g_A2hi, g_A2lo};
    const __nv_bfloat16* Bs[2] = {isZ ? g_Bzhi : g_Brhi, isZ ? g_Bzlo : g_Brlo};
    const float* bb = isZ ? b_z : b_r;
    float acc[4][4][4];
    gemm_mma<0>(smem, As, K23, Bs, K23, m0, n0, K23/BK, acc);

    const int lane = threadIdx.x & 31, wid = threadIdx.x >> 5;
    const int warpm = wid >> 2, warpn = wid & 3;
    const int lrow = lane >> 2, lcol = (lane & 3)*2;
    #pragma unroll
    for (int mt = 0; mt < 4; mt++)
        #pragma unroll
        for (int nt = 0; nt < 4; nt++){
            int n = n0 + warpn*32 + nt*8 + lcol;
            float2 bi = *(const float2*)(bb + n);
            #pragma unroll
            for (int rr = 0; rr < 2; rr++){
                int m = m0 + warpm*64 + mt*16 + lrow + rr*8;
                size_t ho = (size_t)m * DOUT + n;
                float v0 = acc[mt][nt][rr*2+0] + bi.x;
                float v1 = acc[mt][nt][rr*2+1] + bi.y;
                float s0 = 1.f / (1.f + __expf(-v0));
                float s1 = 1.f / (1.f + __expf(-v1));
                if (isZ){
                    *(float2*)(g_z + ho) = make_float2(s0, s1);
                } else {
                    float2 hh = *(const float2*)(h_prev + ho);
                    __nv_bfloat16 h0,l0,h1,l1;
                    split2(s0*hh.x, h0, l0);
                    split2(s1*hh.y, h1, l1);
                    uint32_t hp = (uint32_t)__bfloat16_as_ushort(h0) |
                                  ((uint32_t)__bfloat16_as_ushort(h1) << 16);
                    uint32_t lp = (uint32_t)__bfloat16_as_ushort(l0) |
                                  ((uint32_t)__bfloat16_as_ushort(l1) << 16);
                    size_t ao = (size_t)m * D3 + D2 + n;
                    *(uint32_t*)(g_A3hi + ao) = hp;
                    *(uint32_t*)(g_A3lo + ao) = lp;
                }
            }
        }
}

// ---- kernel 3: candidate + blend (2-way split) ----
__global__ void __launch_bounds__(256, 1)
k3_gemm(const float* __restrict__ h_prev, const float* __restrict__ b_n,
        float* __restrict__ h_out)
{
    extern __shared__ char smem[];
    const int m0 = blockIdx.y * 128, n0 = blockIdx.x * 128;
    const __nv_bfloat16* As[2] = {g_A3hi, g_A3lo};
    const __nv_bfloat16* Bs[2] = {g_Bnhi, g_Bnlo};
    float acc[4][4][4];
    gemm_mma<0>(smem, As, K23, Bs, K23, m0, n0, K23/BK, acc);

    const int lane = threadIdx.x & 31, wid = threadIdx.x >> 5;
    const int warpm = wid >> 2, warpn = wid & 3;
    const int lrow = lane >> 2, lcol = (lane & 3)*2;
    #pragma unroll
    for (int mt = 0; mt < 4; mt++)
        #pragma unroll
        for (int nt = 0; nt < 4; nt++){
            int n = n0 + warpn*32 + nt*8 + lcol;
            float2 bi = *(const float2*)(b_n + n);
            #pragma unroll
            for (int rr = 0; rr < 2; rr++){
                int m = m0 + warpm*64 + mt*16 + lrow + rr*8;
                size_t ho = (size_t)m * DOUT + n;
                float2 hh = *(const float2*)(h_prev + ho);
                float2 zz = *(const float2*)(g_z + ho);
                float n0v = tanhf(acc[mt][nt][rr*2+0] + bi.x);
                float n1v = tanhf(acc[mt][nt][rr*2+1] + bi.y);
                float2 ov = make_float2(hh.x + zz.x*(n0v - hh.x),
                                        hh.y + zz.y*(n1v - hh.y));
                *(float2*)(h_out + ho) = ov;
            }
        }
}

// ---- prep: split x / h_prev into bf16 hi/lo operands; reset fix count ----
__global__ void __launch_bounds__(256)
prep_inputs(const float* __restrict__ x, const float* __restrict__ h)
{
    if (blockIdx.x == 0 && threadIdx.x == 0) g_fix_count = 0;
    int i = blockIdx.x * 256 + threadIdx.x;
    int m = i >> 8, c4 = (i & 255) << 2;
    size_t so = (size_t)m*1024 + c4;
    float4 xv = *(const float4*)(x + so);
    float4 hv = *(const float4*)(h + so);
    float xa[4] = {xv.x,xv.y,xv.z,xv.w};
    float ha[4] = {hv.x,hv.y,hv.z,hv.w};
    __align__(8) __nv_bfloat16 xh[4],xl[4],hh[4],hl[4];
    #pragma unroll
    for (int j = 0; j < 4; j++){
        split2(xa[j], xh[j], xl[j]);
        split2(ha[j], hh[j], hl[j]);
    }
    size_t o1 = (size_t)m*K1 + c4;
    *(uint2*)(g_A1hi + o1) = *(uint2*)xh;
    *(uint2*)(g_A1lo + o1) = *(uint2*)xl;
    *(uint2*)(g_A1hi + o1 + 1024) = *(uint2*)hh;
    *(uint2*)(g_A1lo + o1 + 1024) = *(uint2*)hl;
    size_t o2 = (size_t)m*K23 + D2 + c4;
    *(uint2*)(g_A2hi + o2) = *(uint2*)hh;
    *(uint2*)(g_A2lo + o2) = *(uint2*)hl;
}

// ---- prep: transpose + split weights W[K,N] fp32 -> [N,K] bf16 hi/lo ----
__global__ void __launch_bounds__(256)
transpose_split(const float* __restrict__ W, int K, int N, int which)
{
    __shared__ float t[32][33];
    int n0 = blockIdx.x * 32, k0 = blockIdx.y * 32;
    int tx = threadIdx.x & 31, ty = threadIdx.x >> 5;
    #pragma unroll
    for (int i = 0; i < 32; i += 8)
        t[ty + i][tx] = W[(size_t)(k0 + ty + i)*N + n0 + tx];
    __syncthreads();
    #pragma unroll
    for (int i = 0; i < 32; i += 8){
        int n = n0 + ty + i, k = k0 + tx;
        size_t o = (size_t)n*K + k;
        __nv_bfloat16 h, l;
        split2(t[tx][ty + i], h, l);
        if      (which == 0){ g_B1hi[o] = h; g_B1lo[o] = l; }
        else if (which == 1){ g_Bzhi[o] = h; g_Bzlo[o] = l; }
        else if (which == 2){ g_Brhi[o] = h; g_Brlo[o] = l; }
        else                { g_Bnhi[o] = h; g_Bnlo[o] = l; }
    }
}

// ---- launch ----
extern "C" void kernel_launch(void* const* d_in, const int* in_sizes, int n_in,
                              void* d_out, int out_size)
{
    const float* x        = (const float*)d_in[0];
    const float* h_prev   = (const float*)d_in[1];
    const float* pot_prev = (const float*)d_in[2];
    const float* W_in     = (const float*)d_in[3];
    const float* b_in     = (const float*)d_in[4];
    const float* tresh    = (const float*)d_in[5];
    const float* decay    = (const float*)d_in[6];
    const float* W_z      = (const float*)d_in[7];
    const float* b_z      = (const float*)d_in[8];
    const float* W_r      = (const float*)d_in[9];
    const float* b_r      = (const float*)d_in[10];
    const float* W_n      = (const float*)d_in[11];
    const float* b_n      = (const float*)d_in[12];

    float* h_out   = (float*)d_out;
    float* pot_out = (float*)d_out + (size_t)BATCH * DOUT;

    cudaFuncSetAttribute(k1_gemm, cudaFuncAttributeMaxDynamicSharedMemorySize, SMEM2);
    cudaFuncSetAttribute(k2_gemm, cudaFuncAttributeMaxDynamicSharedMemorySize, SMEM2);
    cudaFuncSetAttribute(k3_gemm, cudaFuncAttributeMaxDynamicSharedMemorySize, SMEM2);

    prep_inputs<<<(BATCH*1024/4)/256, 256>>>(x, h_prev);
    transpose_split<<<dim3(D2/32,   K1/32),  256>>>(W_in, K1,  D2,   0);
    transpose_split<<<dim3(DOUT/32, K23/32), 256>>>(W_z,  K23, DOUT, 1);
    transpose_split<<<dim3(DOUT/32, K23/32), 256>>>(W_r,  K23, DOUT, 2);
    transpose_split<<<dim3(DOUT/32, K23/32), 256>>>(W_n,  K23, DOUT, 3);

    k1_gemm<<<dim3(16, 32), 256, SMEM2>>>(pot_prev, b_in, tresh, decay, pot_out);
    k1_fixup<<<64, 256>>>(x, h_prev, pot_prev, W_in, b_in, tresh, decay, pot_out);
    k2_gemm<<<dim3(16, 32), 256, SMEM2>>>(h_prev, b_z, b_r);
    k3_gemm<<<dim3(8,  32), 256, SMEM2>>>(h_prev, b_n, h_out);
}

// round 12
// speedup vs baseline: 4.6037x; 1.6019x over previous
#include <cuda_runtime.h>
#include <cuda_fp16.h>
#include <stdint.h>
#include <math.h>

#define BATCH 4096
#define DOUT  1024
#define D2    2048
#define D3    3072
#define K1    2048
#define K23   3072

#define BK     32
#define LDS    40                    // padded smem row (fp16 elements)
#define ATILEB (128*LDS*2)           // one 128xBK fp16 tile, bytes (10240)
#define STAGES 3
#define SMEM_K1 (STAGES*3*ATILEB)    // k1: Ahi,Alo,Bhi -> 92160 B
#define SMEM_K23 (STAGES*2*ATILEB)   // k2/k3: Ah,Bh   -> 61440 B

#define MARGIN 1.5e-3f
#define FIXCAP (1<<20)

// ---- scratch (__device__ globals; allocation-free) ----
__device__ __half g_A1hi[(size_t)BATCH*K1];
__device__ __half g_A1lo[(size_t)BATCH*K1];
__device__ __half g_A2h [(size_t)BATCH*K23];
__device__ __half g_A3h [(size_t)BATCH*K23];
__device__ __half g_B1hi[(size_t)D2*K1];
__device__ __half g_B1lo[(size_t)D2*K1];    // only used by fixup reconstruct
__device__ __half g_Bzh [(size_t)DOUT*K23];
__device__ __half g_Brh [(size_t)DOUT*K23];
__device__ __half g_Bnh [(size_t)DOUT*K23];
__device__ float g_z[(size_t)BATCH*DOUT];
__device__ uint32_t g_fix_list[FIXCAP];
__device__ uint32_t g_fix_count;

// ---- helpers ----
__device__ __forceinline__ uint32_t s2u(const void* p){
    uint32_t r;
    asm("{ .reg .u64 t; cvta.to.shared.u64 t, %1; cvt.u32.u64 %0, t; }" : "=r"(r) : "l"(p));
    return r;
}
__device__ __forceinline__ void cp16(uint32_t dst, const void* src){
    asm volatile("cp.async.cg.shared.global [%0], [%1], 16;" :: "r"(dst), "l"(src));
}
__device__ __forceinline__ void ldm4(uint32_t* r, uint32_t a){
    asm volatile("ldmatrix.sync.aligned.m8n8.x4.shared.b16 {%0,%1,%2,%3}, [%4];"
                 : "=r"(r[0]),"=r"(r[1]),"=r"(r[2]),"=r"(r[3]) : "r"(a));
}
__device__ __forceinline__ void mma16816(float* d, const uint32_t* a, uint32_t b0, uint32_t b1){
    asm volatile("mma.sync.aligned.m16n8k16.row.col.f32.f16.f16.f32 "
                 "{%0,%1,%2,%3}, {%4,%5,%6,%7}, {%8,%9}, {%0,%1,%2,%3};"
                 : "+f"(d[0]),"+f"(d[1]),"+f"(d[2]),"+f"(d[3])
                 : "r"(a[0]),"r"(a[1]),"r"(a[2]),"r"(a[3]), "r"(b0),"r"(b1));
}
__device__ __forceinline__ void split2h(float v, __half& h, __half& l){
    h = __float2half(v);
    l = __float2half(v - __half2float(h));
}

// ---- mainloop: NA A-tiles x NB B-tiles, NA*NB passes, fp32 accum ----
template<int NA, int NB>
__device__ __forceinline__ void gemm_mma(char* smem,
    const __half* const* As, int ldA,
    const __half* const* Bs, int ldB,
    int m0, int n0, int nch, float acc[4][4][4])
{
    const int NT = NA + NB;
    const int tid = threadIdx.x, lane = tid & 31, wid = tid >> 5;
    const int warpm = wid >> 2, warpn = wid & 3;     // 2 x 4 warp grid
    const uint32_t sb = s2u(smem);
    const uint32_t stageb = NT*ATILEB;

    #pragma unroll
    for (int i = 0; i < 4; i++)
        #pragma unroll
        for (int j = 0; j < 4; j++)
            #pragma unroll
            for (int q = 0; q < 4; q++) acc[i][j][q] = 0.f;

    #pragma unroll
    for (int c = 0; c < STAGES-1; c++){
        uint32_t st = sb + c*stageb;
        int kt = c * BK;
        #pragma unroll
        for (int t = 0; t < NT; t++){
            const __half* src = (t < NA) ? As[t] : Bs[t-NA];
            int base = (t < NA) ? m0 : n0;
            int ld   = (t < NA) ? ldA : ldB;
            #pragma unroll
            for (int i = 0; i < 2; i++){
                int idx = tid + (i << 8);
                int row = idx >> 2, g = idx & 3;
                uint32_t off = (uint32_t)(row*LDS + g*8)*2;
                cp16(st + t*ATILEB + off, src + (size_t)(base+row)*ld + kt + g*8);
            }
        }
        asm volatile("cp.async.commit_group;");
    }

    for (int c = 0; c < nch; c++){
        asm volatile("cp.async.wait_group %0;" :: "n"(STAGES-2));
        __syncthreads();
        if (c + STAGES-1 < nch){
            uint32_t st = sb + ((c + STAGES-1) % STAGES)*stageb;
            int kt = (c + STAGES-1) * BK;
            #pragma unroll
            for (int t = 0; t < NT; t++){
                const __half* src = (t < NA) ? As[t] : Bs[t-NA];
                int base = (t < NA) ? m0 : n0;
                int ld   = (t < NA) ? ldA : ldB;
                #pragma unroll
                for (int i = 0; i < 2; i++){
                    int idx = tid + (i << 8);
                    int row = idx >> 2, g = idx & 3;
                    uint32_t off = (uint32_t)(row*LDS + g*8)*2;
                    cp16(st + t*ATILEB + off, src + (size_t)(base+row)*ld + kt + g*8);
                }
            }
            asm volatile("cp.async.commit_group;");
        }
        uint32_t st = sb + (c % STAGES)*stageb;
        #pragma unroll
        for (int kk = 0; kk < 2; kk++){
            uint32_t af[NA][4][4], bf[NB][2][4];
            #pragma unroll
            for (int s = 0; s < NA; s++)
                #pragma unroll
                for (int mt = 0; mt < 4; mt++){
                    uint32_t a = st + s*ATILEB + (uint32_t)(((warpm*64 + mt*16 + (lane & 15))*LDS
                                  + kk*16 + (lane >> 4)*8) * 2);
                    ldm4(af[s][mt], a);
                }
            #pragma unroll
            for (int s = 0; s < NB; s++)
                #pragma unroll
                for (int p = 0; p < 2; p++){
                    uint32_t a = st + (NA+s)*ATILEB + (uint32_t)(((warpn*32 + p*16 + (lane & 15))*LDS
                                  + kk*16 + (lane >> 4)*8) * 2);
                    ldm4(bf[s][p], a);
                }
            // small terms first (higher ia = lower magnitude), big last
            #pragma unroll
            for (int ia = NA-1; ia >= 0; ia--)
                #pragma unroll
                for (int ib = NB-1; ib >= 0; ib--)
                    #pragma unroll
                    for (int mt = 0; mt < 4; mt++)
                        #pragma unroll
                        for (int nt = 0; nt < 4; nt++){
                            int p = nt >> 1, o = nt & 1;
                            mma16816(acc[mt][nt], af[ia][mt], bf[ib][p][o], bf[ib][p][o+2]);
                        }
        }
    }
    asm volatile("cp.async.wait_group 0;");
}

// ---- kernel 1: input GEMM (A 2-way fp16 x B-hi, 2 passes) + spike + flag ----
__global__ void __launch_bounds__(256, 1)
k1_gemm(const float* __restrict__ pot_prev, const float* __restrict__ b_in,
        const float* __restrict__ tresh, const float* __restrict__ decay,
        float* __restrict__ pot_out)
{
    extern __shared__ char smem[];
    const int m0 = blockIdx.y * 128, n0 = blockIdx.x * 128;
    const __half* As[2] = {g_A1hi, g_A1lo};
    const __half* Bs[1] = {g_B1hi};
    float acc[4][4][4];
    gemm_mma<2,1>(smem, As, K1, Bs, K1, m0, n0, K1/BK, acc);

    const int lane = threadIdx.x & 31, wid = threadIdx.x >> 5;
    const int warpm = wid >> 2, warpn = wid & 3;
    const int lrow = lane >> 2, lcol = (lane & 3)*2;
    #pragma unroll
    for (int mt = 0; mt < 4; mt++)
        #pragma unroll
        for (int nt = 0; nt < 4; nt++){
            int n = n0 + warpn*32 + nt*8 + lcol;
            float2 bi = *(const float2*)(b_in  + n);
            float2 th = *(const float2*)(tresh + n);
            float2 dc = *(const float2*)(decay + n);
            #pragma unroll
            for (int rr = 0; rr < 2; rr++){
                int m = m0 + warpm*64 + mt*16 + lrow + rr*8;
                size_t po = (size_t)m * D2 + n;
                float2 pp = *(const float2*)(pot_prev + po);
                float p0 = pp.x + acc[mt][nt][rr*2+0] + bi.x;
                float p1 = pp.y + acc[mt][nt][rr*2+1] + bi.y;
                if (fabsf(p0 - th.x) < MARGIN){
                    uint32_t ix = atomicAdd(&g_fix_count, 1u);
                    if (ix < FIXCAP) g_fix_list[ix] = ((uint32_t)m << 11) | (uint32_t)n;
                }
                if (fabsf(p1 - th.y) < MARGIN){
                    uint32_t ix = atomicAdd(&g_fix_count, 1u);
                    if (ix < FIXCAP) g_fix_list[ix] = ((uint32_t)m << 11) | (uint32_t)(n+1);
                }
                bool s0 = p0 > th.x, s1 = p1 > th.y;
                float a0 = s0 ? p0 : 0.f, a1 = s1 ? p1 : 0.f;
                float2 pv = make_float2(s0 ? 0.f : p0*dc.x, s1 ? 0.f : p1*dc.y);
                *(float2*)(pot_out + po) = pv;
                __half2 hp = __floats2half2_rn(a0, a1);
                size_t ao = (size_t)m * D3 + n;
                *(__half2*)(g_A2h + ao) = hp;
                *(__half2*)(g_A3h + ao) = hp;
            }
        }
}

// ---- fixup: exact recompute of flagged elements (coalesced via W^T) ----
__global__ void __launch_bounds__(256)
k1_fixup(const float* __restrict__ x, const float* __restrict__ h,
         const float* __restrict__ pot_prev, const float* __restrict__ b_in,
         const float* __restrict__ tresh, const float* __restrict__ decay,
         float* __restrict__ pot_out)
{
    int lane = threadIdx.x & 31;
    int warp = (blockIdx.x * blockDim.x + threadIdx.x) >> 5;
    int nwarps = (gridDim.x * blockDim.x) >> 5;
    uint32_t cnt = g_fix_count;
    if (cnt > FIXCAP) cnt = FIXCAP;
    for (uint32_t i = warp; i < cnt; i += nwarps){
        uint32_t mn = g_fix_list[i];
        int m = mn >> 11, n = mn & 2047;
        const float* xr = x + (size_t)m * 1024;
        const float* hr = h + (size_t)m * 1024;
        const __half* whi = g_B1hi + (size_t)n * K1;
        const __half* wlo = g_B1lo + (size_t)n * K1;
        float s = 0.f;
        #pragma unroll 4
        for (int k = lane; k < 1024; k += 32)
            s = fmaf(xr[k], __half2float(whi[k]) + __half2float(wlo[k]), s);
        #pragma unroll 4
        for (int k = lane; k < 1024; k += 32)
            s = fmaf(hr[k], __half2float(whi[k+1024]) + __half2float(wlo[k+1024]), s);
        #pragma unroll
        for (int o = 16; o; o >>= 1) s += __shfl_xor_sync(0xFFFFFFFFu, s, o);
        if (lane == 0){
            float pt = pot_prev[(size_t)m * D2 + n] + s + b_in[n];
            bool spk = pt > tresh[n];
            float act = spk ? pt : 0.f;
            pot_out[(size_t)m * D2 + n] = spk ? 0.f : pt * decay[n];
            __half hh = __float2half(act);
            size_t ao = (size_t)m * D3 + n;
            g_A2h[ao] = hh;
            g_A3h[ao] = hh;
        }
    }
}

// ---- kernel 2: z / r gates (pure fp16, 1 pass) ----
__global__ void __launch_bounds__(256, 1)
k2_gemm(const float* __restrict__ h_prev, const float* __restrict__ b_z,
        const float* __restrict__ b_r)
{
    extern __shared__ char smem[];
    const int m0 = blockIdx.y * 128;
    const bool isZ = (blockIdx.x < 8);
    const int n0 = (blockIdx.x & 7) * 128;
    const __half* As[1] = {g_A2h};
    const __half* Bs[1] = {isZ ? g_Bzh : g_Brh};
    const float* bb = isZ ? b_z : b_r;
    float acc[4][4][4];
    gemm_mma<1,1>(smem, As, K23, Bs, K23, m0, n0, K23/BK, acc);

    const int lane = threadIdx.x & 31, wid = threadIdx.x >> 5;
    const int warpm = wid >> 2, warpn = wid & 3;
    const int lrow = lane >> 2, lcol = (lane & 3)*2;
    #pragma unroll
    for (int mt = 0; mt < 4; mt++)
        #pragma unroll
        for (int nt = 0; nt < 4; nt++){
            int n = n0 + warpn*32 + nt*8 + lcol;
            float2 bi = *(const float2*)(bb + n);
            #pragma unroll
            for (int rr = 0; rr < 2; rr++){
                int m = m0 + warpm*64 + mt*16 + lrow + rr*8;
                size_t ho = (size_t)m * DOUT + n;
                float s0 = 1.f / (1.f + __expf(-(acc[mt][nt][rr*2+0] + bi.x)));
                float s1 = 1.f / (1.f + __expf(-(acc[mt][nt][rr*2+1] + bi.y)));
                if (isZ){
                    *(float2*)(g_z + ho) = make_float2(s0, s1);
                } else {
                    float2 hh = *(const float2*)(h_prev + ho);
                    __half2 hp = __floats2half2_rn(s0*hh.x, s1*hh.y);
                    *(__half2*)(g_A3h + (size_t)m * D3 + D2 + n) = hp;
                }
            }
        }
}

// ---- kernel 3: candidate + blend (pure fp16, 1 pass) ----
__global__ void __launch_bounds__(256, 1)
k3_gemm(const float* __restrict__ h_prev, const float* __restrict__ b_n,
        float* __restrict__ h_out)
{
    extern __shared__ char smem[];
    const int m0 = blockIdx.y * 128, n0 = blockIdx.x * 128;
    const __half* As[1] = {g_A3h};
    const __half* Bs[1] = {g_Bnh};
    float acc[4][4][4];
    gemm_mma<1,1>(smem, As, K23, Bs, K23, m0, n0, K23/BK, acc);

    const int lane = threadIdx.x & 31, wid = threadIdx.x >> 5;
    const int warpm = wid >> 2, warpn = wid & 3;
    const int lrow = lane >> 2, lcol = (lane & 3)*2;
    #pragma unroll
    for (int mt = 0; mt < 4; mt++)
        #pragma unroll
        for (int nt = 0; nt < 4; nt++){
            int n = n0 + warpn*32 + nt*8 + lcol;
            float2 bi = *(const float2*)(b_n + n);
            #pragma unroll
            for (int rr = 0; rr < 2; rr++){
                int m = m0 + warpm*64 + mt*16 + lrow + rr*8;
                size_t ho = (size_t)m * DOUT + n;
                float2 hh = *(const float2*)(h_prev + ho);
                float2 zz = *(const float2*)(g_z + ho);
                float n0v = tanhf(acc[mt][nt][rr*2+0] + bi.x);
                float n1v = tanhf(acc[mt][nt][rr*2+1] + bi.y);
                float2 ov = make_float2(hh.x + zz.x*(n0v - hh.x),
                                        hh.y + zz.y*(n1v - hh.y));
                *(float2*)(h_out + ho) = ov;
            }
        }
}

// ---- prep: split x / h_prev into fp16 operands; reset fix count ----
__global__ void __launch_bounds__(256)
prep_inputs(const float* __restrict__ x, const float* __restrict__ h)
{
    if (blockIdx.x == 0 && threadIdx.x == 0) g_fix_count = 0;
    int i = blockIdx.x * 256 + threadIdx.x;
    int m = i >> 8, c4 = (i & 255) << 2;
    size_t so = (size_t)m*1024 + c4;
    float4 xv = *(const float4*)(x + so);
    float4 hv = *(const float4*)(h + so);
    float xa[4] = {xv.x,xv.y,xv.z,xv.w};
    float ha[4] = {hv.x,hv.y,hv.z,hv.w};
    __align__(8) __half xh[4],xl[4],hh[4],hl[4];
    #pragma unroll
    for (int j = 0; j < 4; j++){
        split2h(xa[j], xh[j], xl[j]);
        split2h(ha[j], hh[j], hl[j]);
    }
    size_t o1 = (size_t)m*K1 + c4;
    *(uint2*)(g_A1hi + o1) = *(uint2*)xh;
    *(uint2*)(g_A1lo + o1) = *(uint2*)xl;
    *(uint2*)(g_A1hi + o1 + 1024) = *(uint2*)hh;
    *(uint2*)(g_A1lo + o1 + 1024) = *(uint2*)hl;
    *(uint2*)(g_A2h + (size_t)m*K23 + D2 + c4) = *(uint2*)hh;
}

// ---- prep: transpose + split weights W[K,N] fp32 -> [N,K] fp16 ----
__global__ void __launch_bounds__(256)
transpose_split(const float* __restrict__ W, int K, int N, int which)
{
    __shared__ float t[32][33];
    int n0 = blockIdx.x * 32, k0 = blockIdx.y * 32;
    int tx = threadIdx.x & 31, ty = threadIdx.x >> 5;
    #pragma unroll
    for (int i = 0; i < 32; i += 8)
        t[ty + i][tx] = W[(size_t)(k0 + ty + i)*N + n0 + tx];
    __syncthreads();
    #pragma unroll
    for (int i = 0; i < 32; i += 8){
        int n = n0 + ty + i, k = k0 + tx;
        size_t o = (size_t)n*K + k;
        float v = t[tx][ty + i];
        if (which == 0){
            __half h, l;
            split2h(v, h, l);
            g_B1hi[o] = h; g_B1lo[o] = l;
        } else {
            __half h = __float2half(v);
            if      (which == 1) g_Bzh[o] = h;
            else if (which == 2) g_Brh[o] = h;
            else                 g_Bnh[o] = h;
        }
    }
}

// ---- launch ----
extern "C" void kernel_launch(void* const* d_in, const int* in_sizes, int n_in,
                              void* d_out, int out_size)
{
    const float* x        = (const float*)d_in[0];
    const float* h_prev   = (const float*)d_in[1];
    const float* pot_prev = (const float*)d_in[2];
    const float* W_in     = (const float*)d_in[3];
    const float* b_in     = (const float*)d_in[4];
    const float* tresh    = (const float*)d_in[5];
    const float* decay    = (const float*)d_in[6];
    const float* W_z      = (const float*)d_in[7];
    const float* b_z      = (const float*)d_in[8];
    const float* W_r      = (const float*)d_in[9];
    const float* b_r      = (const float*)d_in[10];
    const float* W_n      = (const float*)d_in[11];
    const float* b_n      = (const float*)d_in[12];

    float* h_out   = (float*)d_out;
    float* pot_out = (float*)d_out + (size_t)BATCH * DOUT;

    cudaFuncSetAttribute(k1_gemm, cudaFuncAttributeMaxDynamicSharedMemorySize, SMEM_K1);
    cudaFuncSetAttribute(k2_gemm, cudaFuncAttributeMaxDynamicSharedMemorySize, SMEM_K23);
    cudaFuncSetAttribute(k3_gemm, cudaFuncAttributeMaxDynamicSharedMemorySize, SMEM_K23);

    prep_inputs<<<(BATCH*1024/4)/256, 256>>>(x, h_prev);
    transpose_split<<<dim3(D2/32,   K1/32),  256>>>(W_in, K1,  D2,   0);
    transpose_split<<<dim3(DOUT/32, K23/32), 256>>>(W_z,  K23, DOUT, 1);
    transpose_split<<<dim3(DOUT/32, K23/32), 256>>>(W_r,  K23, DOUT, 2);
    transpose_split<<<dim3(DOUT/32, K23/32), 256>>>(W_n,  K23, DOUT, 3);

    k1_gemm<<<dim3(16, 32), 256, SMEM_K1>>>(pot_prev, b_in, tresh, decay, pot_out);
    k1_fixup<<<64, 256>>>(x, h_prev, pot_prev, b_in, tresh, decay, pot_out);
    k2_gemm<<<dim3(16, 32), 256, SMEM_K23>>>(h_prev, b_z, b_r);
    k3_gemm<<<dim3(8,  32), 256, SMEM_K23>>>(h_prev, b_n, h_out);
}